// round 15
// baseline (speedup 1.0000x reference)
#include <cuda_runtime.h>
#include <cuda_bf16.h>
#include <cuda_fp8.h>
#include <cstdint>

#define L 6400
#define C 256
#define HW 80
#define MARG 2
#define THRESH 0.2f
// sim = dot / (C * 0.1f)
#define SCALE (1.0f / 25.6f)
#define CAND_MAX 65536

// ---------------- device scratch (no allocations allowed) ----------------
__device__ uint8_t g_A8[L * C];                  // fp8 e4m3 copies
__device__ uint8_t g_B8[L * C];
__device__ __nv_bfloat16 g_Ebf[(size_t)L * L];   // exp(sim) bf16 — written ONLY on fallback
__device__ float g_rowsum[L];                    // pass1: raw sim-acc row sums; fallback: exp sums
__device__ float g_colsum[L];
__device__ float g_invrs[L];
__device__ float g_invcs[L];
__device__ unsigned g_simmax_key;                // order-encoded float (raw acc), atomicMax
__device__ int g_flag;                           // 1 -> candidates possible (fallback)
__device__ int g_ncand;
__device__ uint4 g_cand[CAND_MAX];               // {row, col, conf_bits, pad}

// conf computed bit-identically in fallback-capture and resolve
__device__ __forceinline__ float conf_fn(float e, float irs, float ics) {
    return __fmul_rn(__fmul_rn(e, irs), __fmul_rn(e, ics));
}

__device__ __forceinline__ bool interior(int idx) {
    int i0 = idx / HW;
    int j0 = idx - i0 * HW;
    return ((unsigned)(i0 - MARG) < (unsigned)(HW - 2 * MARG)) &&
           ((unsigned)(j0 - MARG) < (unsigned)(HW - 2 * MARG));
}

// monotone float<->uint encoding (handles negatives) for atomicMax
__device__ __forceinline__ unsigned enc_f(float f) {
    unsigned b = __float_as_uint(f);
    return b ^ ((unsigned)((int)b >> 31) | 0x80000000u);
}
__device__ __forceinline__ float dec_f(unsigned k) {
    unsigned b = (k & 0x80000000u) ? (k ^ 0x80000000u) : ~k;
    return __uint_as_float(b);
}

// ---------------- fp32 -> fp8 conversion (+ init) ----------------
__global__ void k_convert(const float* __restrict__ x0, const float* __restrict__ x1) {
    int i = blockIdx.x * blockDim.x + threadIdx.x;   // over L*C/4
    if (i < L) { g_rowsum[i] = 0.f; g_colsum[i] = 0.f; }
    if (i == 0) {
        g_ncand = 0;
        g_simmax_key = 0u;
        g_flag = 0;
    }
    if (i >= L * C / 4) return;
    float4 a = ((const float4*)x0)[i];
    float4 b = ((const float4*)x1)[i];
    unsigned pa = (unsigned)__nv_cvt_float2_to_fp8x2(make_float2(a.x, a.y), __NV_SATFINITE, __NV_E4M3)
                | ((unsigned)__nv_cvt_float2_to_fp8x2(make_float2(a.z, a.w), __NV_SATFINITE, __NV_E4M3) << 16);
    unsigned pb = (unsigned)__nv_cvt_float2_to_fp8x2(make_float2(b.x, b.y), __NV_SATFINITE, __NV_E4M3)
                | ((unsigned)__nv_cvt_float2_to_fp8x2(make_float2(b.z, b.w), __NV_SATFINITE, __NV_E4M3) << 16);
    ((unsigned*)g_A8)[i] = pa;
    ((unsigned*)g_B8)[i] = pb;
}

// ---------------- shared fp8 GEMM mainloop (BM=BN=128, BK=64 bytes) ----------------
#define BM 128
#define BN 128
#define BKB 64      // k-bytes per stage
#define PADB 80     // row stride in bytes (16B aligned, conflict-free ldmatrix)
#define STAGE_B (BM * PADB)            // 10240 B
#define SMEM_MAIN (4 * STAGE_B)        // As[2] + Bs[2] = 40 KB

// computes acc[4][4][4] for this warp's tile partition
#define GEMM_MAINLOOP(ACC)                                                              \
    {                                                                                   \
        auto as_of = [&](int s_) { return base + (uint32_t)s_ * STAGE_B; };             \
        auto bs_of = [&](int s_) { return base + 2u * STAGE_B + (uint32_t)s_ * STAGE_B; };\
        auto prefetch = [&](int kb, int s_) {                                           \
            _Pragma("unroll")                                                           \
            for (int t = 0; t < 2; t++) {                                               \
                int idx = tid + t * 256;                                                \
                int row = idx >> 2;                                                     \
                int ch  = idx & 3;                                                      \
                uint32_t off = (uint32_t)(row * PADB + ch * 16);                        \
                const void* sa = (const void*)(g_A8 + (size_t)(m0 + row) * C + kb + ch * 16);\
                const void* sb = (const void*)(g_B8 + (size_t)(n0 + row) * C + kb + ch * 16);\
                asm volatile("cp.async.cg.shared.global [%0],[%1],16;\n" :: "r"(as_of(s_) + off), "l"(sa));\
                asm volatile("cp.async.cg.shared.global [%0],[%1],16;\n" :: "r"(bs_of(s_) + off), "l"(sb));\
            }                                                                           \
        };                                                                              \
        prefetch(0, 0);                                                                 \
        asm volatile("cp.async.commit_group;\n");                                       \
        int s = 0;                                                                      \
        for (int kbi = 0; kbi < C / BKB; kbi++) {                                       \
            if (kbi + 1 < C / BKB) {                                                    \
                prefetch((kbi + 1) * BKB, s ^ 1);                                       \
                asm volatile("cp.async.commit_group;\n");                               \
                asm volatile("cp.async.wait_group 1;\n");                               \
            } else {                                                                    \
                asm volatile("cp.async.wait_group 0;\n");                               \
            }                                                                           \
            __syncthreads();                                                            \
            const uint32_t as_base = as_of(s);                                          \
            const uint32_t bs_base = bs_of(s);                                          \
            _Pragma("unroll")                                                           \
            for (int kk = 0; kk < 2; kk++) {                                            \
                uint32_t a[4][4], b[4][2];                                              \
                _Pragma("unroll")                                                       \
                for (int mi = 0; mi < 4; mi++) {                                        \
                    int mrow = wm * 64 + mi * 16 + (lane & 15);                         \
                    int kcol = kk * 32 + ((lane >> 4) << 4);                            \
                    uint32_t addr = as_base + (uint32_t)(mrow * PADB + kcol);           \
                    asm volatile(                                                       \
                        "ldmatrix.sync.aligned.m8n8.x4.shared.b16 {%0,%1,%2,%3},[%4];"  \
                        : "=r"(a[mi][0]), "=r"(a[mi][1]), "=r"(a[mi][2]), "=r"(a[mi][3])\
                        : "r"(addr));                                                   \
                }                                                                       \
                _Pragma("unroll")                                                       \
                for (int p = 0; p < 2; p++) {                                           \
                    int g  = lane >> 3;                                                 \
                    int lr = lane & 7;                                                  \
                    int nrow = wn * 32 + (2 * p + (g >> 1)) * 8 + lr;                   \
                    int kcol = kk * 32 + (g & 1) * 16;                                  \
                    uint32_t addr = bs_base + (uint32_t)(nrow * PADB + kcol);           \
                    asm volatile(                                                       \
                        "ldmatrix.sync.aligned.m8n8.x4.shared.b16 {%0,%1,%2,%3},[%4];"  \
                        : "=r"(b[2 * p][0]), "=r"(b[2 * p][1]),                         \
                          "=r"(b[2 * p + 1][0]), "=r"(b[2 * p + 1][1])                  \
                        : "r"(addr));                                                   \
                }                                                                       \
                _Pragma("unroll")                                                       \
                for (int mi = 0; mi < 4; mi++)                                          \
                    _Pragma("unroll")                                                   \
                    for (int ni = 0; ni < 4; ni++) {                                    \
                        asm volatile(                                                   \
                            "mma.sync.aligned.m16n8k32.row.col.f32.e4m3.e4m3.f32 "      \
                            "{%0,%1,%2,%3},{%4,%5,%6,%7},{%8,%9},{%0,%1,%2,%3};"        \
                            : "+f"(ACC[mi][ni][0]), "+f"(ACC[mi][ni][1]),               \
                              "+f"(ACC[mi][ni][2]), "+f"(ACC[mi][ni][3])                \
                            : "r"(a[mi][0]), "r"(a[mi][1]), "r"(a[mi][2]), "r"(a[mi][3]),\
                              "r"(b[ni][0]), "r"(b[ni][1]));                            \
                    }                                                                   \
            }                                                                           \
            __syncthreads();                                                            \
            s ^= 1;                                                                     \
        }                                                                               \
    }

// epilogue reduction helper: per-warp partials -> smem srow/scol, then global atomics
#define EPILOGUE_REDUCE(ROWP, COLP)                                                     \
    {                                                                                   \
        _Pragma("unroll")                                                               \
        for (int mi = 0; mi < 4; mi++)                                                  \
            _Pragma("unroll")                                                           \
            for (int h = 0; h < 2; h++) {                                               \
                float p = ROWP[mi][h];                                                  \
                p += __shfl_xor_sync(0xffffffffu, p, 1);                                \
                p += __shfl_xor_sync(0xffffffffu, p, 2);                                \
                if (qc == 0) atomicAdd(&srow[wm * 64 + mi * 16 + qr + h * 8], p);       \
            }                                                                           \
        _Pragma("unroll")                                                               \
        for (int ni = 0; ni < 4; ni++)                                                  \
            _Pragma("unroll")                                                           \
            for (int h = 0; h < 2; h++) {                                               \
                float p = COLP[ni][h];                                                  \
                p += __shfl_xor_sync(0xffffffffu, p, 4);                                \
                p += __shfl_xor_sync(0xffffffffu, p, 8);                                \
                p += __shfl_xor_sync(0xffffffffu, p, 16);                               \
                if (qr == 0) atomicAdd(&scol[wn * 32 + ni * 8 + qc * 2 + h], p);        \
            }                                                                           \
        __syncthreads();                                                                \
        if (tid < BM) {                                                                 \
            atomicAdd(&g_rowsum[m0 + tid], srow[tid]);                                  \
            atomicAdd(&g_colsum[n0 + tid], scol[tid]);                                  \
        }                                                                               \
    }

// ---------------- pass 1: screening GEMM (raw sim sums + global max; ZERO exp) ----------------
__global__ void __launch_bounds__(256) k_gemm_stats() {
    __shared__ __align__(16) char sm_raw[SMEM_MAIN];
    __shared__ float srow[BM];
    __shared__ float scol[BN];

    const int tid  = threadIdx.x;
    const int lane = tid & 31;
    const int wid  = tid >> 5;
    const int wm   = wid >> 2;
    const int wn   = wid & 3;
    const int m0   = blockIdx.y * BM;
    const int n0   = blockIdx.x * BN;
    const uint32_t base = (uint32_t)__cvta_generic_to_shared(sm_raw);

    if (tid < BM) { srow[tid] = 0.f; scol[tid] = 0.f; }

    float acc[4][4][4];
#pragma unroll
    for (int mi = 0; mi < 4; mi++)
#pragma unroll
        for (int ni = 0; ni < 4; ni++)
#pragma unroll
            for (int j = 0; j < 4; j++) acc[mi][ni][j] = 0.f;

    GEMM_MAINLOOP(acc)

    const int qr = lane >> 2;
    const int qc = lane & 3;
    float rowp[4][2], colp[4][2];
#pragma unroll
    for (int i = 0; i < 4; i++) { rowp[i][0] = rowp[i][1] = 0.f; colp[i][0] = colp[i][1] = 0.f; }
    float amax = -1e30f;

#pragma unroll
    for (int mi = 0; mi < 4; mi++)
#pragma unroll
        for (int ni = 0; ni < 4; ni++) {
            float a0 = acc[mi][ni][0], a1 = acc[mi][ni][1];
            float a2 = acc[mi][ni][2], a3 = acc[mi][ni][3];
            amax = fmaxf(amax, fmaxf(fmaxf(a0, a1), fmaxf(a2, a3)));
            rowp[mi][0] += a0 + a1;
            rowp[mi][1] += a2 + a3;
            colp[ni][0] += a0 + a2;
            colp[ni][1] += a1 + a3;
        }
#pragma unroll
    for (int o = 16; o; o >>= 1) amax = fmaxf(amax, __shfl_xor_sync(0xffffffffu, amax, o));
    if (lane == 0) atomicMax(&g_simmax_key, enc_f(amax));

    EPILOGUE_REDUCE(rowp, colp)
}

// ---------------- flag: Jensen lower bounds, set fallback flag; re-init sums if fallback ----------------
__global__ void __launch_bounds__(256) k_flag() {
    __shared__ float sred[2][8];
    const int tid = threadIdx.x, lane = tid & 31, w = tid >> 5;
    float rmin = 1e30f, cmin = 1e30f;
    for (int i = tid; i < L; i += 256) {
        rmin = fminf(rmin, g_rowsum[i]);
        cmin = fminf(cmin, g_colsum[i]);
    }
#pragma unroll
    for (int o = 16; o; o >>= 1) {
        rmin = fminf(rmin, __shfl_xor_sync(0xffffffffu, rmin, o));
        cmin = fminf(cmin, __shfl_xor_sync(0xffffffffu, cmin, o));
    }
    if (lane == 0) { sred[0][w] = rmin; sred[1][w] = cmin; }
    __syncthreads();
    if (tid == 0) {
        float rm = sred[0][0], cm = sred[1][0];
#pragma unroll
        for (int k = 1; k < 8; k++) { rm = fminf(rm, sred[0][k]); cm = fminf(cm, sred[1][k]); }
        float smax = dec_f(g_simmax_key) * SCALE;          // max sim
        const float lnL = 8.76405f;                        // ln(6400)
        // Jensen: rowsum_exp >= L * exp(mean sim)  ->  ln >= lnL + SCALE*rawsum/L
        float ln_rs_lb = lnL + rm * (SCALE / (float)L);
        float ln_cs_lb = lnL + cm * (SCALE / (float)L);
        // conf <= exp(2*smax - ln_rs - ln_cs); 2.0-nat margin >> fp8 error (~0.25 nat)
        g_flag = (2.f * smax - ln_rs_lb - ln_cs_lb >= -1.60944f - 2.0f) ? 1 : 0;
    }
    __syncthreads();
    // fallback prep: exp-sums will be re-accumulated into g_rowsum/g_colsum
    if (g_flag) {
        for (int i = tid; i < L; i += 256) { g_rowsum[i] = 0.f; g_colsum[i] = 0.f; }
    }
}

// ---------------- fallback pass A (gated): exp-based row/col sums ----------------
__global__ void __launch_bounds__(256) k_fb_sums() {
    if (g_flag == 0) return;
    __shared__ __align__(16) char sm_raw[SMEM_MAIN];
    __shared__ float srow[BM];
    __shared__ float scol[BN];

    const int tid  = threadIdx.x;
    const int lane = tid & 31;
    const int wid  = tid >> 5;
    const int wm   = wid >> 2;
    const int wn   = wid & 3;
    const int m0   = blockIdx.y * BM;
    const int n0   = blockIdx.x * BN;
    const uint32_t base = (uint32_t)__cvta_generic_to_shared(sm_raw);

    if (tid < BM) { srow[tid] = 0.f; scol[tid] = 0.f; }

    float acc[4][4][4];
#pragma unroll
    for (int mi = 0; mi < 4; mi++)
#pragma unroll
        for (int ni = 0; ni < 4; ni++)
#pragma unroll
            for (int j = 0; j < 4; j++) acc[mi][ni][j] = 0.f;

    GEMM_MAINLOOP(acc)

    const int qr = lane >> 2;
    const int qc = lane & 3;
    float rowp[4][2], colp[4][2];
#pragma unroll
    for (int i = 0; i < 4; i++) { rowp[i][0] = rowp[i][1] = 0.f; colp[i][0] = colp[i][1] = 0.f; }

#pragma unroll
    for (int mi = 0; mi < 4; mi++)
#pragma unroll
        for (int ni = 0; ni < 4; ni++) {
            float e0 = __expf(acc[mi][ni][0] * SCALE);
            float e1 = __expf(acc[mi][ni][1] * SCALE);
            float e2 = __expf(acc[mi][ni][2] * SCALE);
            float e3 = __expf(acc[mi][ni][3] * SCALE);
            rowp[mi][0] += e0 + e1;
            rowp[mi][1] += e2 + e3;
            colp[ni][0] += e0 + e2;
            colp[ni][1] += e1 + e3;
        }

    EPILOGUE_REDUCE(rowp, colp)
}

// ---------------- fallback pass B (gated): reciprocals ----------------
__global__ void k_fb_post() {
    if (g_flag == 0) return;
    int i = blockIdx.x * blockDim.x + threadIdx.x;
    if (i < L) {
        g_invrs[i] = 1.0f / g_rowsum[i];
        g_invcs[i] = 1.0f / g_colsum[i];
    }
}

// ---------------- pass 2: zero output; gated fallback (store E + candidates) ----------------
__global__ void __launch_bounds__(256) k_zero_or_scan(float* __restrict__ out) {
    __shared__ __align__(16) char sm_raw[SMEM_MAIN];

    const int tid  = threadIdx.x;
    const int lane = tid & 31;
    const int wid  = tid >> 5;
    const int wm   = wid >> 2;
    const int wn   = wid & 3;
    const int m0   = blockIdx.y * BM;
    const int n0   = blockIdx.x * BN;
    const uint32_t base = (uint32_t)__cvta_generic_to_shared(sm_raw);

    // always: zero this 128x128 output tile (coalesced float4)
    const float4 z = make_float4(0.f, 0.f, 0.f, 0.f);
#pragma unroll
    for (int it = 0; it < 16; it++) {
        int row = it * 8 + wid;
        *(float4*)&out[(size_t)(m0 + row) * L + n0 + lane * 4] = z;
    }

    if (g_flag == 0) return;   // uniform across grid

    // ---- fallback: recompute sim, store E bf16, capture candidates ----
    float acc[4][4][4];
#pragma unroll
    for (int mi = 0; mi < 4; mi++)
#pragma unroll
        for (int ni = 0; ni < 4; ni++)
#pragma unroll
            for (int j = 0; j < 4; j++) acc[mi][ni][j] = 0.f;

    GEMM_MAINLOOP(acc)

    const int qr = lane >> 2;
    const int qc = lane & 3;
#pragma unroll
    for (int mi = 0; mi < 4; mi++) {
        int gr0 = m0 + wm * 64 + mi * 16 + qr;
        float irs0 = g_invrs[gr0], irs1 = g_invrs[gr0 + 8];
#pragma unroll
        for (int ni = 0; ni < 4; ni++) {
            int gc = n0 + wn * 32 + ni * 8 + qc * 2;
            float ics0 = g_invcs[gc], ics1 = g_invcs[gc + 1];
            __nv_bfloat162 lo = __floats2bfloat162_rn(__expf(acc[mi][ni][0] * SCALE),
                                                      __expf(acc[mi][ni][1] * SCALE));
            __nv_bfloat162 hi = __floats2bfloat162_rn(__expf(acc[mi][ni][2] * SCALE),
                                                      __expf(acc[mi][ni][3] * SCALE));
            *(__nv_bfloat162*)&g_Ebf[(size_t)gr0 * L + gc]       = lo;
            *(__nv_bfloat162*)&g_Ebf[(size_t)(gr0 + 8) * L + gc] = hi;
            float f0 = conf_fn(__bfloat162float(lo.x), irs0, ics0);
            float f1 = conf_fn(__bfloat162float(lo.y), irs0, ics1);
            float f2 = conf_fn(__bfloat162float(hi.x), irs1, ics0);
            float f3 = conf_fn(__bfloat162float(hi.y), irs1, ics1);
            if (f0 > THRESH) { int ix = atomicAdd(&g_ncand, 1); if (ix < CAND_MAX) g_cand[ix] = make_uint4(gr0,     gc,     __float_as_uint(f0), 0); }
            if (f1 > THRESH) { int ix = atomicAdd(&g_ncand, 1); if (ix < CAND_MAX) g_cand[ix] = make_uint4(gr0,     gc + 1, __float_as_uint(f1), 0); }
            if (f2 > THRESH) { int ix = atomicAdd(&g_ncand, 1); if (ix < CAND_MAX) g_cand[ix] = make_uint4(gr0 + 8, gc,     __float_as_uint(f2), 0); }
            if (f3 > THRESH) { int ix = atomicAdd(&g_ncand, 1); if (ix < CAND_MAX) g_cand[ix] = make_uint4(gr0 + 8, gc + 1, __float_as_uint(f3), 0); }
        }
    }
}

// ---------------- pass 3: per-candidate row/col max, write sparse nonzeros ----------------
__global__ void __launch_bounds__(256) k_resolve(float* __restrict__ out) {
    __shared__ float sred[2][8];
    int n = g_ncand;
    if (n > CAND_MAX) n = CAND_MAX;
    const int tid = threadIdx.x, lane = tid & 31, w = tid >> 5;

    for (int ci = blockIdx.x; ci < n; ci += gridDim.x) {
        uint4 cd = g_cand[ci];
        int r = (int)cd.x, c = (int)cd.y;
        unsigned bits = cd.z;
        float irs = g_invrs[r];
        float ics = g_invcs[c];

        float rm = 0.f, cm = 0.f;
        for (int j = tid; j < L; j += 256) {
            rm = fmaxf(rm, conf_fn(__bfloat162float(g_Ebf[(size_t)r * L + j]), irs, g_invcs[j]));
            cm = fmaxf(cm, conf_fn(__bfloat162float(g_Ebf[(size_t)j * L + c]), g_invrs[j], ics));
        }
#pragma unroll
        for (int o = 16; o; o >>= 1) {
            rm = fmaxf(rm, __shfl_xor_sync(0xffffffffu, rm, o));
            cm = fmaxf(cm, __shfl_xor_sync(0xffffffffu, cm, o));
        }
        if (lane == 0) { sred[0][w] = rm; sred[1][w] = cm; }
        __syncthreads();
        if (tid == 0) {
            float rmax = sred[0][0], cmax = sred[1][0];
#pragma unroll
            for (int k = 1; k < 8; k++) {
                rmax = fmaxf(rmax, sred[0][k]);
                cmax = fmaxf(cmax, sred[1][k]);
            }
            if (bits == __float_as_uint(rmax) && bits == __float_as_uint(cmax) &&
                interior(r) && interior(c)) {
                out[(size_t)r * L + c] = __uint_as_float(bits);
            }
        }
        __syncthreads();
    }
}

// ---------------- launch ----------------
extern "C" void kernel_launch(void* const* d_in, const int* in_sizes, int n_in,
                              void* d_out, int out_size) {
    const float* x0 = (const float*)d_in[0];
    const float* x1 = (const float*)d_in[1];
    float* out = (float*)d_out;

    k_convert<<<(L * C / 4 + 255) / 256, 256>>>(x0, x1);

    dim3 grid(L / BN, L / BM);   // 50 x 50
    k_gemm_stats<<<grid, 256>>>();
    k_flag<<<1, 256>>>();
    k_fb_sums<<<grid, 256>>>();          // no-op unless g_flag
    k_fb_post<<<(L + 255) / 256, 256>>>();
    k_zero_or_scan<<<grid, 256>>>(out);
    k_resolve<<<64, 256>>>(out);
}

// round 16
// speedup vs baseline: 1.2844x; 1.2844x over previous
#include <cuda_runtime.h>
#include <cuda_bf16.h>
#include <cuda_fp8.h>
#include <cstdint>

#define L 6400
#define C 256
#define HW 80
#define MARG 2
#define THRESH 0.2f
// sim = dot / (C * 0.1f)
#define SCALE (1.0f / 25.6f)

// ---------------- device scratch (no allocations allowed) ----------------
__device__ uint8_t g_A8[L * C];                  // fp8 e4m3 copies
__device__ uint8_t g_B8[L * C];
__device__ __nv_bfloat16 g_Ebf[(size_t)L * L];   // exp(sim) bf16 — written ONLY on fallback
__device__ float g_rowsum[L];                    // raw sim-acc row sums (screening)
__device__ float g_colsum[L];
__device__ float g_ersum[L];                     // exp sums (fallback only)
__device__ float g_ecsum[L];
__device__ float g_invrs[L];
__device__ float g_invcs[L];
__device__ unsigned g_simmax_key;                // order-encoded float (raw acc), atomicMax
__device__ int g_flag;                           // 1 -> candidates possible (fallback)
__device__ int g_done;                           // completion counters (self-resetting)
__device__ int g_done2;

// conf computed bit-identically in fallback scan and inline resolve
__device__ __forceinline__ float conf_fn(float e, float irs, float ics) {
    return __fmul_rn(__fmul_rn(e, irs), __fmul_rn(e, ics));
}

__device__ __forceinline__ bool interior(int idx) {
    int i0 = idx / HW;
    int j0 = idx - i0 * HW;
    return ((unsigned)(i0 - MARG) < (unsigned)(HW - 2 * MARG)) &&
           ((unsigned)(j0 - MARG) < (unsigned)(HW - 2 * MARG));
}

// monotone float<->uint encoding (handles negatives) for atomicMax
__device__ __forceinline__ unsigned enc_f(float f) {
    unsigned b = __float_as_uint(f);
    return b ^ ((unsigned)((int)b >> 31) | 0x80000000u);
}
__device__ __forceinline__ float dec_f(unsigned k) {
    unsigned b = (k & 0x80000000u) ? (k ^ 0x80000000u) : ~k;
    return __uint_as_float(b);
}

// ---------------- fp32 -> fp8 conversion (+ init) ----------------
__global__ void k_convert(const float* __restrict__ x0, const float* __restrict__ x1) {
    int i = blockIdx.x * blockDim.x + threadIdx.x;   // over L*C/4
    if (i < L) {
        g_rowsum[i] = 0.f; g_colsum[i] = 0.f;
        g_ersum[i] = 0.f;  g_ecsum[i] = 0.f;
    }
    if (i == 0) { g_simmax_key = 0u; g_flag = 0; }
    if (i >= L * C / 4) return;
    float4 a = ((const float4*)x0)[i];
    float4 b = ((const float4*)x1)[i];
    unsigned pa = (unsigned)__nv_cvt_float2_to_fp8x2(make_float2(a.x, a.y), __NV_SATFINITE, __NV_E4M3)
                | ((unsigned)__nv_cvt_float2_to_fp8x2(make_float2(a.z, a.w), __NV_SATFINITE, __NV_E4M3) << 16);
    unsigned pb = (unsigned)__nv_cvt_float2_to_fp8x2(make_float2(b.x, b.y), __NV_SATFINITE, __NV_E4M3)
                | ((unsigned)__nv_cvt_float2_to_fp8x2(make_float2(b.z, b.w), __NV_SATFINITE, __NV_E4M3) << 16);
    ((unsigned*)g_A8)[i] = pa;
    ((unsigned*)g_B8)[i] = pb;
}

// ---------------- fp8 GEMM mainloop: block tile 128x64, BK=64 bytes ----------------
#define BM 128
#define BN 64
#define BKB 64
#define PADB 80
#define STAGE_A 10240          // 128*80
#define STAGE_BB 5120          // 64*80
#define SMEM_MAIN (2 * STAGE_A + 2 * STAGE_BB)   // 30720 B
#define GRID_X (L / BN)        // 100
#define GRID_Y (L / BM)        // 50
#define GRID_TILES (GRID_X * GRID_Y)

// computes ACC[4][2][4] for this warp's 64x16 partition (wm: 0..1, wn: 0..3)
#define GEMM_MAINLOOP(ACC)                                                              \
    {                                                                                   \
        auto as_of = [&](int s_) { return base + (uint32_t)s_ * STAGE_A; };             \
        auto bs_of = [&](int s_) { return base + 2u * STAGE_A + (uint32_t)s_ * STAGE_BB; };\
        auto prefetch = [&](int kb, int s_) {                                           \
            _Pragma("unroll")                                                           \
            for (int t = 0; t < 2; t++) {                                               \
                int idx = tid + t * 256;                                                \
                int row = idx >> 2;                                                     \
                int ch  = idx & 3;                                                      \
                const void* sa = (const void*)(g_A8 + (size_t)(m0 + row) * C + kb + ch * 16);\
                asm volatile("cp.async.cg.shared.global [%0],[%1],16;\n"                \
                             :: "r"(as_of(s_) + (uint32_t)(row * PADB + ch * 16)), "l"(sa));\
            }                                                                           \
            {                                                                           \
                int row = tid >> 2;                                                     \
                int ch  = tid & 3;                                                      \
                const void* sb = (const void*)(g_B8 + (size_t)(n0 + row) * C + kb + ch * 16);\
                asm volatile("cp.async.cg.shared.global [%0],[%1],16;\n"                \
                             :: "r"(bs_of(s_) + (uint32_t)(row * PADB + ch * 16)), "l"(sb));\
            }                                                                           \
        };                                                                              \
        prefetch(0, 0);                                                                 \
        asm volatile("cp.async.commit_group;\n");                                       \
        int s = 0;                                                                      \
        for (int kbi = 0; kbi < C / BKB; kbi++) {                                       \
            if (kbi + 1 < C / BKB) {                                                    \
                prefetch((kbi + 1) * BKB, s ^ 1);                                       \
                asm volatile("cp.async.commit_group;\n");                               \
                asm volatile("cp.async.wait_group 1;\n");                               \
            } else {                                                                    \
                asm volatile("cp.async.wait_group 0;\n");                               \
            }                                                                           \
            __syncthreads();                                                            \
            const uint32_t as_base = as_of(s);                                          \
            const uint32_t bs_base = bs_of(s);                                          \
            _Pragma("unroll")                                                           \
            for (int kk = 0; kk < 2; kk++) {                                            \
                uint32_t a[4][4], b[2][2];                                              \
                _Pragma("unroll")                                                       \
                for (int mi = 0; mi < 4; mi++) {                                        \
                    int mrow = wm * 64 + mi * 16 + (lane & 15);                         \
                    int kcol = kk * 32 + ((lane >> 4) << 4);                            \
                    uint32_t addr = as_base + (uint32_t)(mrow * PADB + kcol);           \
                    asm volatile(                                                       \
                        "ldmatrix.sync.aligned.m8n8.x4.shared.b16 {%0,%1,%2,%3},[%4];"  \
                        : "=r"(a[mi][0]), "=r"(a[mi][1]), "=r"(a[mi][2]), "=r"(a[mi][3])\
                        : "r"(addr));                                                   \
                }                                                                       \
                {                                                                       \
                    int g  = lane >> 3;                                                 \
                    int lr = lane & 7;                                                  \
                    int nrow = wn * 16 + (g >> 1) * 8 + lr;                             \
                    int kcol = kk * 32 + (g & 1) * 16;                                  \
                    uint32_t addr = bs_base + (uint32_t)(nrow * PADB + kcol);           \
                    asm volatile(                                                       \
                        "ldmatrix.sync.aligned.m8n8.x4.shared.b16 {%0,%1,%2,%3},[%4];"  \
                        : "=r"(b[0][0]), "=r"(b[0][1]), "=r"(b[1][0]), "=r"(b[1][1])    \
                        : "r"(addr));                                                   \
                }                                                                       \
                _Pragma("unroll")                                                       \
                for (int mi = 0; mi < 4; mi++)                                          \
                    _Pragma("unroll")                                                   \
                    for (int ni = 0; ni < 2; ni++) {                                    \
                        asm volatile(                                                   \
                            "mma.sync.aligned.m16n8k32.row.col.f32.e4m3.e4m3.f32 "      \
                            "{%0,%1,%2,%3},{%4,%5,%6,%7},{%8,%9},{%0,%1,%2,%3};"        \
                            : "+f"(ACC[mi][ni][0]), "+f"(ACC[mi][ni][1]),               \
                              "+f"(ACC[mi][ni][2]), "+f"(ACC[mi][ni][3])                \
                            : "r"(a[mi][0]), "r"(a[mi][1]), "r"(a[mi][2]), "r"(a[mi][3]),\
                              "r"(b[ni][0]), "r"(b[ni][1]));                            \
                    }                                                                   \
            }                                                                           \
            __syncthreads();                                                            \
            s ^= 1;                                                                     \
        }                                                                               \
    }

// per-warp partials -> smem srow/scol -> global atomics (RS/CS = global arrays)
#define EPILOGUE_REDUCE(ROWP, COLP, RS, CS)                                             \
    {                                                                                   \
        _Pragma("unroll")                                                               \
        for (int mi = 0; mi < 4; mi++)                                                  \
            _Pragma("unroll")                                                           \
            for (int h = 0; h < 2; h++) {                                               \
                float p = ROWP[mi][h];                                                  \
                p += __shfl_xor_sync(0xffffffffu, p, 1);                                \
                p += __shfl_xor_sync(0xffffffffu, p, 2);                                \
                if (qc == 0) atomicAdd(&srow[wm * 64 + mi * 16 + qr + h * 8], p);       \
            }                                                                           \
        _Pragma("unroll")                                                               \
        for (int ni = 0; ni < 2; ni++)                                                  \
            _Pragma("unroll")                                                           \
            for (int h = 0; h < 2; h++) {                                               \
                float p = COLP[ni][h];                                                  \
                p += __shfl_xor_sync(0xffffffffu, p, 4);                                \
                p += __shfl_xor_sync(0xffffffffu, p, 8);                                \
                p += __shfl_xor_sync(0xffffffffu, p, 16);                               \
                if (qr == 0) atomicAdd(&scol[wn * 16 + ni * 8 + qc * 2 + h], p);        \
            }                                                                           \
        __syncthreads();                                                                \
        if (tid < BM) atomicAdd(&RS[m0 + tid], srow[tid]);                              \
        if (tid < BN) atomicAdd(&CS[n0 + tid], scol[tid]);                              \
    }

// ---------------- pass 1: GEMM (raw sums + max) + zero output tile + last-block flag ----
__global__ void __launch_bounds__(256, 3) k_gemm_stats(float* __restrict__ out) {
    __shared__ __align__(16) char sm_raw[SMEM_MAIN];
    __shared__ float srow[BM];
    __shared__ float scol[BN];
    __shared__ int sIsLast;
    __shared__ float sred[2][8];

    const int tid  = threadIdx.x;
    const int lane = tid & 31;
    const int wid  = tid >> 5;
    const int wm   = wid >> 2;   // 0..1 (64 rows)
    const int wn   = wid & 3;    // 0..3 (16 cols)
    const int m0   = blockIdx.y * BM;
    const int n0   = blockIdx.x * BN;
    const uint32_t base = (uint32_t)__cvta_generic_to_shared(sm_raw);

    if (tid < BM) srow[tid] = 0.f;
    if (tid < BN) scol[tid] = 0.f;

    float acc[4][2][4];
#pragma unroll
    for (int mi = 0; mi < 4; mi++)
#pragma unroll
        for (int ni = 0; ni < 2; ni++)
#pragma unroll
            for (int j = 0; j < 4; j++) acc[mi][ni][j] = 0.f;

    GEMM_MAINLOOP(acc)

    // zero this block's output tile (always correct except rare patched candidates)
    {
        const float4 z = make_float4(0.f, 0.f, 0.f, 0.f);
        const int row16 = tid >> 4;    // 0..15
        const int l16   = tid & 15;
#pragma unroll
        for (int it = 0; it < 8; it++) {
            int row = it * 16 + row16;
            *(float4*)&out[(size_t)(m0 + row) * L + n0 + l16 * 4] = z;
        }
    }

    const int qr = lane >> 2;
    const int qc = lane & 3;
    float rowp[4][2], colp[2][2];
#pragma unroll
    for (int i = 0; i < 4; i++) { rowp[i][0] = rowp[i][1] = 0.f; }
    colp[0][0] = colp[0][1] = colp[1][0] = colp[1][1] = 0.f;
    float amax = -1e30f;

#pragma unroll
    for (int mi = 0; mi < 4; mi++)
#pragma unroll
        for (int ni = 0; ni < 2; ni++) {
            float a0 = acc[mi][ni][0], a1 = acc[mi][ni][1];
            float a2 = acc[mi][ni][2], a3 = acc[mi][ni][3];
            amax = fmaxf(amax, fmaxf(fmaxf(a0, a1), fmaxf(a2, a3)));
            rowp[mi][0] += a0 + a1;
            rowp[mi][1] += a2 + a3;
            colp[ni][0] += a0 + a2;
            colp[ni][1] += a1 + a3;
        }
#pragma unroll
    for (int o = 16; o; o >>= 1) amax = fmaxf(amax, __shfl_xor_sync(0xffffffffu, amax, o));
    if (lane == 0) atomicMax(&g_simmax_key, enc_f(amax));

    EPILOGUE_REDUCE(rowp, colp, g_rowsum, g_colsum)

    // ---- last-block: compute screening flag ----
    __threadfence();
    if (tid == 0) {
        int d = atomicAdd(&g_done, 1);
        sIsLast = (d == GRID_TILES - 1);
    }
    __syncthreads();
    if (!sIsLast) return;

    float rmin = 1e30f, cmin = 1e30f;
    for (int i = tid; i < L; i += 256) {
        rmin = fminf(rmin, g_rowsum[i]);
        cmin = fminf(cmin, g_colsum[i]);
    }
#pragma unroll
    for (int o = 16; o; o >>= 1) {
        rmin = fminf(rmin, __shfl_xor_sync(0xffffffffu, rmin, o));
        cmin = fminf(cmin, __shfl_xor_sync(0xffffffffu, cmin, o));
    }
    if (lane == 0) { sred[0][wid] = rmin; sred[1][wid] = cmin; }
    __syncthreads();
    if (tid == 0) {
        float rm = sred[0][0], cm = sred[1][0];
#pragma unroll
        for (int k = 1; k < 8; k++) { rm = fminf(rm, sred[0][k]); cm = fminf(cm, sred[1][k]); }
        float smax = dec_f(g_simmax_key) * SCALE;          // max sim
        const float lnL = 8.76405f;                        // ln(6400)
        // Jensen: rowsum_exp >= L * exp(mean sim)  ->  ln >= lnL + SCALE*rawsum/L
        float ln_rs_lb = lnL + rm * (SCALE / (float)L);
        float ln_cs_lb = lnL + cm * (SCALE / (float)L);
        // conf <= exp(2*smax - ln_rs - ln_cs); 2.0-nat margin >> fp8 error
        g_flag = (2.f * smax - ln_rs_lb - ln_cs_lb >= -1.60944f - 2.0f) ? 1 : 0;
        g_done = 0;   // reset for next graph replay
    }
}

// ---------------- fallback A (gated): exp sums + E store + last-block recips ----------
__global__ void __launch_bounds__(256) k_fb_sums() {
    if (g_flag == 0) return;
    __shared__ __align__(16) char sm_raw[SMEM_MAIN];
    __shared__ float srow[BM];
    __shared__ float scol[BN];
    __shared__ int sIsLast;

    const int tid  = threadIdx.x;
    const int lane = tid & 31;
    const int wid  = tid >> 5;
    const int wm   = wid >> 2;
    const int wn   = wid & 3;
    const int m0   = blockIdx.y * BM;
    const int n0   = blockIdx.x * BN;
    const uint32_t base = (uint32_t)__cvta_generic_to_shared(sm_raw);

    if (tid < BM) srow[tid] = 0.f;
    if (tid < BN) scol[tid] = 0.f;

    float acc[4][2][4];
#pragma unroll
    for (int mi = 0; mi < 4; mi++)
#pragma unroll
        for (int ni = 0; ni < 2; ni++)
#pragma unroll
            for (int j = 0; j < 4; j++) acc[mi][ni][j] = 0.f;

    GEMM_MAINLOOP(acc)

    const int qr = lane >> 2;
    const int qc = lane & 3;
    float rowp[4][2], colp[2][2];
#pragma unroll
    for (int i = 0; i < 4; i++) { rowp[i][0] = rowp[i][1] = 0.f; }
    colp[0][0] = colp[0][1] = colp[1][0] = colp[1][1] = 0.f;

#pragma unroll
    for (int mi = 0; mi < 4; mi++) {
        int gr0 = m0 + wm * 64 + mi * 16 + qr;
#pragma unroll
        for (int ni = 0; ni < 2; ni++) {
            int gc = n0 + wn * 16 + ni * 8 + qc * 2;
            float e0 = __expf(acc[mi][ni][0] * SCALE);
            float e1 = __expf(acc[mi][ni][1] * SCALE);
            float e2 = __expf(acc[mi][ni][2] * SCALE);
            float e3 = __expf(acc[mi][ni][3] * SCALE);
            __nv_bfloat162 lo = __floats2bfloat162_rn(e0, e1);
            __nv_bfloat162 hi = __floats2bfloat162_rn(e2, e3);
            *(__nv_bfloat162*)&g_Ebf[(size_t)gr0 * L + gc]       = lo;
            *(__nv_bfloat162*)&g_Ebf[(size_t)(gr0 + 8) * L + gc] = hi;
            // sums of the bf16-rounded values (bit-consistent with scan)
            rowp[mi][0] += __bfloat162float(lo.x) + __bfloat162float(lo.y);
            rowp[mi][1] += __bfloat162float(hi.x) + __bfloat162float(hi.y);
            colp[ni][0] += __bfloat162float(lo.x) + __bfloat162float(hi.x);
            colp[ni][1] += __bfloat162float(lo.y) + __bfloat162float(hi.y);
        }
    }

    EPILOGUE_REDUCE(rowp, colp, g_ersum, g_ecsum)

    __threadfence();
    if (tid == 0) {
        int d = atomicAdd(&g_done2, 1);
        sIsLast = (d == GRID_TILES - 1);
    }
    __syncthreads();
    if (!sIsLast) return;
    for (int i = tid; i < L; i += 256) {
        g_invrs[i] = 1.0f / g_ersum[i];
        g_invcs[i] = 1.0f / g_ecsum[i];
    }
    if (tid == 0) g_done2 = 0;
}

// ---------------- fallback B (gated): conf scan + inline mutual-max resolve -----------
__global__ void __launch_bounds__(256) k_fb_scan(float* __restrict__ out) {
    if (g_flag == 0) return;
    const int tid = threadIdx.x, lane = tid & 31, w = tid >> 5;
    const int r0 = blockIdx.y * 128, c0 = blockIdx.x * 128;
    const int c = c0 + lane * 4;

    const float ics0 = g_invcs[c + 0], ics1 = g_invcs[c + 1];
    const float ics2 = g_invcs[c + 2], ics3 = g_invcs[c + 3];

    auto resolve = [&](int r, int cc, float f) {
        float irs = g_invrs[r];
        float ics = g_invcs[cc];
        float rm = 0.f, cm = 0.f;
        for (int j = 0; j < L; j++) {
            rm = fmaxf(rm, conf_fn(__bfloat162float(g_Ebf[(size_t)r * L + j]), irs, g_invcs[j]));
            cm = fmaxf(cm, conf_fn(__bfloat162float(g_Ebf[(size_t)j * L + cc]), g_invrs[j], ics));
        }
        if (__float_as_uint(f) == __float_as_uint(rm) &&
            __float_as_uint(f) == __float_as_uint(cm) &&
            interior(r) && interior(cc)) {
            out[(size_t)r * L + cc] = f;
        }
    };

#pragma unroll 4
    for (int i = 0; i < 16; i++) {
        int r = r0 + w + i * 8;
        float irs = g_invrs[r];
        uint2 raw = *(const uint2*)&g_Ebf[(size_t)r * L + c];
        __nv_bfloat162 p01 = *(__nv_bfloat162*)&raw.x;
        __nv_bfloat162 p23 = *(__nv_bfloat162*)&raw.y;
        float f0 = conf_fn(__bfloat162float(p01.x), irs, ics0);
        float f1 = conf_fn(__bfloat162float(p01.y), irs, ics1);
        float f2 = conf_fn(__bfloat162float(p23.x), irs, ics2);
        float f3 = conf_fn(__bfloat162float(p23.y), irs, ics3);
        if (fmaxf(fmaxf(f0, f1), fmaxf(f2, f3)) > THRESH) {   // structurally ~never
            if (f0 > THRESH) resolve(r, c + 0, f0);
            if (f1 > THRESH) resolve(r, c + 1, f1);
            if (f2 > THRESH) resolve(r, c + 2, f2);
            if (f3 > THRESH) resolve(r, c + 3, f3);
        }
    }
}

// ---------------- launch ----------------
extern "C" void kernel_launch(void* const* d_in, const int* in_sizes, int n_in,
                              void* d_out, int out_size) {
    const float* x0 = (const float*)d_in[0];
    const float* x1 = (const float*)d_in[1];
    float* out = (float*)d_out;

    k_convert<<<(L * C / 4 + 255) / 256, 256>>>(x0, x1);

    dim3 grid(GRID_X, GRID_Y);           // 100 x 50
    k_gemm_stats<<<grid, 256>>>(out);    // zero + raw sums + max + flag
    k_fb_sums<<<grid, 256>>>();          // no-op unless g_flag
    dim3 grid2(L / 128, L / 128);        // 50 x 50
    k_fb_scan<<<grid2, 256>>>(out);      // no-op unless g_flag
}